// round 12
// baseline (speedup 1.0000x reference)
#include <cuda_runtime.h>
#include <cuda_fp16.h>
#include <mma.h>

using namespace nvcuda;

// Problem constants
#define Bc 4
#define Hc 16
#define Sc 2048
#define Dc 128
#define NTOT (Bc * Hc * Sc * Dc)

// Tiling
#define TQ 256
#define TK 64
#define THREADS 512
#define NWARP 16
#define NKT (Sc / TK)
#define LDH 136
#define PFL 68
#define PHL 72

#define QH_HALF (TQ * LDH)
#define KV_TILE_HALF (TK * LDH)
#define PW_FLOATS 1088
#define SMEM_BYTES (QH_HALF * 2 + 4 * KV_TILE_HALF * 2 + NWARP * PW_FLOATS * 4)

// fp16 copies of Q/K/V (pre-pass output). Static device scratch: allowed.
__device__ __half g_qh[NTOT];
__device__ __half g_kh[NTOT];
__device__ __half g_vh[NTOT];

// cp.async helpers (identical asm forms to the rounds that compiled cleanly)
__device__ __forceinline__ void cp_async16(void* s, const void* g) {
    unsigned sa = (unsigned)__cvta_generic_to_shared(s);
    asm volatile("cp.async.cg.shared.global [%0],[%1],16;\n" ::"r"(sa), "l"(g));
}
__device__ __forceinline__ void cp_commit() { asm volatile("cp.async.commit_group;\n"); }
__device__ __forceinline__ void cp_wait0() { asm volatile("cp.async.wait_group 0;\n"); }
__device__ __forceinline__ void cp_wait1() { asm volatile("cp.async.wait_group 1;\n"); }

// exp for small x via degree-6 Taylor; __expf fallback for the rare tail
__device__ __forceinline__ float exp_small(float x) {
    float pe = 1.388888889e-3f;
    pe = fmaf(pe, x, 8.333333333e-3f);
    pe = fmaf(pe, x, 4.166666667e-2f);
    pe = fmaf(pe, x, 1.666666667e-1f);
    pe = fmaf(pe, x, 0.5f);
    pe = fmaf(pe, x, 1.0f);
    pe = fmaf(pe, x, 1.0f);
    if (fabsf(x) > 0.5f) {
        pe = __expf(x);
    }
    return pe;
}

// Pre-pass: fp32 to fp16 RN conversion of Q, K, V
__global__ __launch_bounds__(256)
void cvt_kernel(const float4* __restrict__ q,
                const float4* __restrict__ k,
                const float4* __restrict__ v) {
    int i = blockIdx.x * blockDim.x + threadIdx.x;
    float4 a;
    __half2 h0, h1;
    uint2 u;

    a = q[i];
    h0 = __floats2half2_rn(a.x, a.y);
    h1 = __floats2half2_rn(a.z, a.w);
    u.x = *(unsigned*)&h0;
    u.y = *(unsigned*)&h1;
    ((uint2*)g_qh)[i] = u;

    a = k[i];
    h0 = __floats2half2_rn(a.x, a.y);
    h1 = __floats2half2_rn(a.z, a.w);
    u.x = *(unsigned*)&h0;
    u.y = *(unsigned*)&h1;
    ((uint2*)g_kh)[i] = u;

    a = v[i];
    h0 = __floats2half2_rn(a.x, a.y);
    h1 = __floats2half2_rn(a.z, a.w);
    u.x = *(unsigned*)&h0;
    u.y = *(unsigned*)&h1;
    ((uint2*)g_vh)[i] = u;
}

__global__ __launch_bounds__(THREADS, 1)
void attn_main_kernel(const float* __restrict__ mg,
                      float* __restrict__ outg,
                      float* __restrict__ attng) {
    extern __shared__ __half sh[];
    const int tid  = threadIdx.x;
    const int lane = tid & 31;
    const int w    = tid >> 5;

    const int hh = blockIdx.x;
    const int qt = blockIdx.y;
    const int b  = blockIdx.z;
    const int q0 = qt * TQ;

    const long long bh = (long long)b * Hc + hh;
    const __half* qg = g_qh + (bh * Sc + q0) * (long long)Dc;
    const __half* kb = g_kh + bh * Sc * (long long)Dc;
    const __half* vb = g_vh + bh * Sc * (long long)Dc;

    __half* kvbase = sh + QH_HALF;
    float*  pw = (float*)(sh + QH_HALF + 4 * KV_TILE_HALF) + w * PW_FLOATS;

    // Prologue: Q tile (256 x 128) then K0/V0, both via cp.async
    #pragma unroll
    for (int i = 0; i < 8; ++i) {
        int cid = tid + i * THREADS;
        int r = cid >> 4;
        int c = (cid & 15) * 8;
        cp_async16(sh + r * LDH + c, qg + r * Dc + c);
    }
    cp_commit();
    #pragma unroll
    for (int i = 0; i < 2; ++i) {
        int cid = tid + i * THREADS;
        int r = cid >> 4;
        int c = (cid & 15) * 8;
        cp_async16(kvbase + r * LDH + c, kb + r * Dc + c);
        cp_async16(kvbase + KV_TILE_HALF + r * LDH + c, vb + r * Dc + c);
    }
    cp_commit();

    // Per-warp state
    wmma::fragment<wmma::accumulator, 16, 16, 16, float> Oacc[8];
    #pragma unroll
    for (int j = 0; j < 8; ++j) {
        wmma::fill_fragment(Oacc[j], 0.0f);
    }
    float lsum = 0.0f;

    const int row = lane >> 1;
    const int cb  = (lane & 1) * 32;
    const int row_glob = q0 + 16 * w + row;
    const float* mrow = mg + ((long long)b * Sc + row_glob) * Sc;
    const long long out_row = bh * Sc + row_glob;
    float* arow = attng ? (attng + out_row * (long long)Sc) : nullptr;
    const __half* qrow = sh + 16 * w * LDH;

    for (int kt = 0; kt < NKT; ++kt) {
        __syncthreads();   // all warps done with the buffer about to be refilled

        if (kt + 1 < NKT) {
            const __half* kp = kb + (long long)(kt + 1) * TK * Dc;
            const __half* vp = vb + (long long)(kt + 1) * TK * Dc;
            __half* kd = kvbase + ((kt + 1) & 1) * (2 * KV_TILE_HALF);
            #pragma unroll
            for (int i = 0; i < 2; ++i) {
                int cid = tid + i * THREADS;
                int r = cid >> 4;
                int c = (cid & 15) * 8;
                cp_async16(kd + r * LDH + c, kp + r * Dc + c);
                cp_async16(kd + KV_TILE_HALF + r * LDH + c, vp + r * Dc + c);
            }
            cp_commit();
            cp_wait1();
        } else {
            cp_wait0();
        }
        __syncthreads();   // stage kt visible to all warps

        const __half* Kc = kvbase + (kt & 1) * (2 * KV_TILE_HALF);
        const __half* Vc = Kc + KV_TILE_HALF;

        // QK for this warp's 16 rows: 4 key n-tiles x 8 k-steps
        #pragma unroll
        for (int j = 0; j < 4; ++j) {
            wmma::fragment<wmma::accumulator, 16, 16, 16, float> sacc;
            wmma::fill_fragment(sacc, 0.0f);
            #pragma unroll
            for (int k = 0; k < 8; ++k) {
                wmma::fragment<wmma::matrix_a, 16, 16, 16, __half, wmma::row_major> af;
                wmma::fragment<wmma::matrix_b, 16, 16, 16, __half, wmma::col_major> bf;
                wmma::load_matrix_sync(af, qrow + k * 16, LDH);
                wmma::load_matrix_sync(bf, Kc + j * 16 * LDH + k * 16, LDH);
                wmma::mma_sync(sacc, af, bf, sacc);
            }
            wmma::store_matrix_sync(pw + j * 16, sacc, PFL, wmma::mem_row_major);
        }
        __syncwarp();

        // Elementwise on the warp-private tile: read all S first (overlay safety)
        float s[32];
        {
            const float* srow = pw + row * PFL + cb;
            #pragma unroll
            for (int i = 0; i < 8; ++i) {
                float4 t = *(const float4*)(srow + i * 4);
                s[4 * i + 0] = t.x;
                s[4 * i + 1] = t.y;
                s[4 * i + 2] = t.z;
                s[4 * i + 3] = t.w;
            }
        }
        __syncwarp();

        {
            const float* mk = mrow + (long long)kt * TK + cb;
            float* ak = arow ? (arow + (long long)kt * TK + cb) : nullptr;
            __half* phw = (__half*)pw + row * PHL + cb;
            #pragma unroll
            for (int i = 0; i < 8; ++i) {
                float4 m4 = *(const float4*)(mk + i * 4);
                float p0 = exp_small(s[4 * i + 0] * 0.0078125f);
                float p1 = exp_small(s[4 * i + 1] * 0.0078125f);
                float p2 = exp_small(s[4 * i + 2] * 0.0078125f);
                float p3 = exp_small(s[4 * i + 3] * 0.0078125f);
                p0 = (m4.x != 0.0f) ? 0.0f : p0;
                p1 = (m4.y != 0.0f) ? 0.0f : p1;
                p2 = (m4.z != 0.0f) ? 0.0f : p2;
                p3 = (m4.w != 0.0f) ? 0.0f : p3;
                if (ak) {
                    *(float4*)(ak + i * 4) = make_float4(p0, p1, p2, p3);
                }
                lsum += p0 + p1 + p2 + p3;
                __half2 a01 = __floats2half2_rn(p0, p1);
                __half2 a23 = __floats2half2_rn(p2, p3);
                uint2 u;
                u.x = *(unsigned*)&a01;
                u.y = *(unsigned*)&a23;
                *(uint2*)(phw + i * 4) = u;
            }
        }
        __syncwarp();

        // PV: 4 key k-steps x 8 d n-tiles, accumulate into persistent Oacc
        const __half* ph = (const __half*)pw;
        #pragma unroll
        for (int k = 0; k < 4; ++k) {
            wmma::fragment<wmma::matrix_a, 16, 16, 16, __half, wmma::row_major> af;
            wmma::load_matrix_sync(af, ph + k * 16, PHL);
            #pragma unroll
            for (int j2 = 0; j2 < 8; ++j2) {
                wmma::fragment<wmma::matrix_b, 16, 16, 16, __half, wmma::row_major> bf;
                wmma::load_matrix_sync(bf, Vc + k * 16 * LDH + j2 * 16, LDH);
                wmma::mma_sync(Oacc[j2], af, bf, Oacc[j2]);
            }
        }
    }

    // Row sums: 2 lanes per row
    lsum += __shfl_xor_sync(0xffffffffu, lsum, 1);
    const float inv = 1.0f / lsum;

    // Output: stage Oacc through the warp-private tile in two d-chunks
    #pragma unroll
    for (int dhf = 0; dhf < 2; ++dhf) {
        __syncwarp();
        #pragma unroll
        for (int jj = 0; jj < 4; ++jj) {
            wmma::store_matrix_sync(pw + jj * 16, Oacc[dhf * 4 + jj], PFL,
                                    wmma::mem_row_major);
        }
        __syncwarp();
        const float* srow = pw + row * PFL + cb;
        float* orow = outg + out_row * (long long)Dc + dhf * 64 + cb;
        #pragma unroll
        for (int i = 0; i < 8; ++i) {
            float4 t = *(const float4*)(srow + i * 4);
            t.x *= inv;
            t.y *= inv;
            t.z *= inv;
            t.w *= inv;
            *(float4*)(orow + i * 4) = t;
        }
    }
}

// Kernel 2: normalize each attn row in place (measured at DRAM roofline)
__global__ __launch_bounds__(256, 8)
void attn_norm_kernel(float* __restrict__ attn) {
    const long long row = blockIdx.x;
    float4* rp = (float4*)(attn + row * (long long)Sc);
    const int t = threadIdx.x;

    float4 a = rp[t];
    float4 b = rp[t + 256];
    float s = a.x + a.y + a.z + a.w + b.x + b.y + b.z + b.w;
    #pragma unroll
    for (int o = 16; o > 0; o >>= 1) {
        s += __shfl_xor_sync(0xffffffffu, s, o);
    }

    __shared__ float red[8];
    if ((t & 31) == 0) {
        red[t >> 5] = s;
    }
    __syncthreads();
    float tot = red[0] + red[1] + red[2] + red[3] + red[4] + red[5] + red[6] + red[7];
    float inv = 1.0f / tot;

    a.x *= inv; a.y *= inv; a.z *= inv; a.w *= inv;
    b.x *= inv; b.y *= inv; b.z *= inv; b.w *= inv;
    rp[t] = a;
    rp[t + 256] = b;
}

extern "C" void kernel_launch(void* const* d_in, const int* in_sizes, int n_in,
                              void* d_out, int out_size) {
    const float* q = (const float*)d_in[0];
    const float* k = (const float*)d_in[1];
    const float* v = (const float*)d_in[2];
    const float* m = (const float*)d_in[3];
    float* out = (float*)d_out;

    const long long OUT_ELE = (long long)Bc * Hc * Sc * Dc;
    float* attn = ((long long)out_size > OUT_ELE) ? (out + OUT_ELE) : nullptr;

    cudaFuncSetAttribute(attn_main_kernel,
                         cudaFuncAttributeMaxDynamicSharedMemorySize, SMEM_BYTES);
    cudaFuncSetAttribute(attn_main_kernel,
                         cudaFuncAttributePreferredSharedMemoryCarveout, 100);

    cvt_kernel<<<NTOT / 4 / 256, 256>>>((const float4*)q, (const float4*)k,
                                        (const float4*)v);

    dim3 grid1(Hc, Sc / TQ, Bc);
    attn_main_kernel<<<grid1, THREADS, SMEM_BYTES>>>(m, out, attn);

    if (attn) {
        attn_norm_kernel<<<(long long)Bc * Hc * Sc, 256>>>(attn);
    }
}

// round 13
// speedup vs baseline: 1.0090x; 1.0090x over previous
#include <cuda_runtime.h>
#include <cuda_fp16.h>
#include <mma.h>

using namespace nvcuda;

// Problem constants
#define Bc 4
#define Hc 16
#define Sc 2048
#define Dc 128
#define NTOT (Bc * Hc * Sc * Dc)

// Tiling: 4 warps per CTA, each warp owns 16 query rows end-to-end
#define TQ 64
#define TK 64
#define THREADS 128
#define NKT (Sc / TK)
#define LDH 136
#define PFL 68
#define PHL 72

// smem layout in halves:
//   Q tile        at 0        size 8704
//   KV stages     at 8704     size 34816  (2 stages, each K tile then V tile)
//   S scratch     at 43520    size 8704   (4 warps, 16 x PFL floats each)
//   P scratch     at 52224    size 4608   (4 warps, 16 x PHL halves each)
//   row sums      at 56832    size 128    (64 floats)
#define QOFF 0
#define KVOFF 8704
#define KVSTAGE 17408
#define SFOFF 43520
#define PHOFF 52224
#define LROFF 56832
#define SMEM_BYTES ((56832 + 128) * 2)

// fp16 copies of Q/K/V (pre-pass output). Static device scratch: allowed.
__device__ __half g_qh[NTOT];
__device__ __half g_kh[NTOT];
__device__ __half g_vh[NTOT];

// cp.async helpers (identical asm forms to the rounds that compiled cleanly)
__device__ __forceinline__ void cp_async16(void* s, const void* g) {
    unsigned sa = (unsigned)__cvta_generic_to_shared(s);
    asm volatile("cp.async.cg.shared.global [%0],[%1],16;\n" ::"r"(sa), "l"(g));
}
__device__ __forceinline__ void cp_commit() { asm volatile("cp.async.commit_group;\n"); }
__device__ __forceinline__ void cp_wait0() { asm volatile("cp.async.wait_group 0;\n"); }
__device__ __forceinline__ void cp_wait1() { asm volatile("cp.async.wait_group 1;\n"); }

// exp for small x via degree-6 Taylor; __expf fallback for the rare tail
__device__ __forceinline__ float exp_small(float x) {
    float pe = 1.388888889e-3f;
    pe = fmaf(pe, x, 8.333333333e-3f);
    pe = fmaf(pe, x, 4.166666667e-2f);
    pe = fmaf(pe, x, 1.666666667e-1f);
    pe = fmaf(pe, x, 0.5f);
    pe = fmaf(pe, x, 1.0f);
    pe = fmaf(pe, x, 1.0f);
    if (fabsf(x) > 0.5f) {
        pe = __expf(x);
    }
    return pe;
}

// Pre-pass: fp32 to fp16 RN conversion of Q, K, V
__global__ __launch_bounds__(256)
void cvt_kernel(const float4* __restrict__ q,
                const float4* __restrict__ k,
                const float4* __restrict__ v) {
    int i = blockIdx.x * blockDim.x + threadIdx.x;
    float4 a;
    __half2 h0, h1;
    uint2 u;

    a = q[i];
    h0 = __floats2half2_rn(a.x, a.y);
    h1 = __floats2half2_rn(a.z, a.w);
    u.x = *(unsigned*)&h0;
    u.y = *(unsigned*)&h1;
    ((uint2*)g_qh)[i] = u;

    a = k[i];
    h0 = __floats2half2_rn(a.x, a.y);
    h1 = __floats2half2_rn(a.z, a.w);
    u.x = *(unsigned*)&h0;
    u.y = *(unsigned*)&h1;
    ((uint2*)g_kh)[i] = u;

    a = v[i];
    h0 = __floats2half2_rn(a.x, a.y);
    h1 = __floats2half2_rn(a.z, a.w);
    u.x = *(unsigned*)&h0;
    u.y = *(unsigned*)&h1;
    ((uint2*)g_vh)[i] = u;
}

__global__ __launch_bounds__(THREADS, 2)
void attn_main_kernel(const float* __restrict__ mg,
                      float* __restrict__ outg,
                      float* __restrict__ attng) {
    extern __shared__ __half sh[];
    const int tid  = threadIdx.x;
    const int lane = tid & 31;
    const int w    = tid >> 5;

    const int hh = blockIdx.x;
    const int qt = blockIdx.y;
    const int b  = blockIdx.z;
    const int q0 = qt * TQ;

    const long long bh = (long long)b * Hc + hh;
    const __half* qg = g_qh + (bh * Sc + q0) * (long long)Dc;
    const __half* kb = g_kh + bh * Sc * (long long)Dc;
    const __half* vb = g_vh + bh * Sc * (long long)Dc;

    __half* Qs    = sh + QOFF;
    __half* kvs   = sh + KVOFF;
    float*  pw    = (float*)(sh + SFOFF) + w * 16 * PFL;
    __half* phw   = sh + PHOFF + w * 16 * PHL;
    float*  lrowW = (float*)(sh + LROFF);

    // Prologue: Q tile, then K0/V0 stage
    #pragma unroll
    for (int i = 0; i < 8; ++i) {
        int cid = tid + i * THREADS;
        int r = cid >> 4;
        int c = (cid & 15) * 8;
        cp_async16(Qs + r * LDH + c, qg + r * Dc + c);
    }
    cp_commit();
    #pragma unroll
    for (int i = 0; i < 8; ++i) {
        int cid = tid + i * THREADS;
        int r = cid >> 4;
        int c = (cid & 15) * 8;
        cp_async16(kvs + r * LDH + c, kb + r * Dc + c);
        cp_async16(kvs + TK * LDH + r * LDH + c, vb + r * Dc + c);
    }
    cp_commit();

    // Per-warp persistent state: O accumulators and per-row partial sums
    wmma::fragment<wmma::accumulator, 16, 16, 16, float> Oacc[8];
    #pragma unroll
    for (int j = 0; j < 8; ++j) {
        wmma::fill_fragment(Oacc[j], 0.0f);
    }
    float lsr[8];
    #pragma unroll
    for (int i = 0; i < 8; ++i) {
        lsr[i] = 0.0f;
    }

    // Exp-phase lane mapping: 16 lanes sweep one row contiguously, 2 rows at once
    const int half = lane >> 4;
    const int cl   = lane & 15;
    const int c0   = cl * 4;
    const long long mbase =
        (((long long)b * Sc) + q0 + 16 * w + half) * (long long)Sc + c0;
    const long long abase =
        ((bh * Sc) + q0 + 16 * w + half) * (long long)Sc + c0;

    for (int kt = 0; kt < NKT; ++kt) {
        __syncthreads();   // all warps finished reading the buffer we refill next

        if (kt + 1 < NKT) {
            const __half* kp = kb + (long long)(kt + 1) * TK * Dc;
            const __half* vp = vb + (long long)(kt + 1) * TK * Dc;
            __half* kd = kvs + ((kt + 1) & 1) * KVSTAGE;
            #pragma unroll
            for (int i = 0; i < 8; ++i) {
                int cid = tid + i * THREADS;
                int r = cid >> 4;
                int c = (cid & 15) * 8;
                cp_async16(kd + r * LDH + c, kp + r * Dc + c);
                cp_async16(kd + TK * LDH + r * LDH + c, vp + r * Dc + c);
            }
            cp_commit();
            cp_wait1();
        } else {
            cp_wait0();
        }
        __syncthreads();   // stage kt (and Q on first iter) visible to all warps

        const __half* Kc = kvs + (kt & 1) * KVSTAGE;
        const __half* Vc = Kc + TK * LDH;

        // QK for this warp's 16 rows: hoisted Q fragment, 4 key column tiles
        {
            wmma::fragment<wmma::accumulator, 16, 16, 16, float> sacc[4];
            #pragma unroll
            for (int j = 0; j < 4; ++j) {
                wmma::fill_fragment(sacc[j], 0.0f);
            }
            #pragma unroll
            for (int k = 0; k < 8; ++k) {
                wmma::fragment<wmma::matrix_a, 16, 16, 16, __half, wmma::row_major> af;
                wmma::load_matrix_sync(af, Qs + 16 * w * LDH + k * 16, LDH);
                #pragma unroll
                for (int j = 0; j < 4; ++j) {
                    wmma::fragment<wmma::matrix_b, 16, 16, 16, __half, wmma::col_major> bf;
                    wmma::load_matrix_sync(bf, Kc + j * 16 * LDH + k * 16, LDH);
                    wmma::mma_sync(sacc[j], af, bf, sacc[j]);
                }
            }
            #pragma unroll
            for (int j = 0; j < 4; ++j) {
                wmma::store_matrix_sync(pw + j * 16, sacc[j], PFL, wmma::mem_row_major);
            }
        }
        __syncwarp();

        // Elementwise on this warp's private tile, coalesced per row
        {
            const float* mk = mg + mbase + (long long)kt * TK;
            float* ak = attng ? (attng + abase + (long long)kt * TK) : nullptr;
            #pragma unroll
            for (int i = 0; i < 8; ++i) {
                int r = 2 * i + half;
                float4 s4 = *(const float4*)(pw + r * PFL + c0);
                float4 m4 = *(const float4*)(mk + 2 * i * (long long)Sc);
                float p0 = exp_small(s4.x * 0.0078125f);
                float p1 = exp_small(s4.y * 0.0078125f);
                float p2 = exp_small(s4.z * 0.0078125f);
                float p3 = exp_small(s4.w * 0.0078125f);
                p0 = (m4.x != 0.0f) ? 0.0f : p0;
                p1 = (m4.y != 0.0f) ? 0.0f : p1;
                p2 = (m4.z != 0.0f) ? 0.0f : p2;
                p3 = (m4.w != 0.0f) ? 0.0f : p3;
                if (ak) {
                    *(float4*)(ak + 2 * i * (long long)Sc) = make_float4(p0, p1, p2, p3);
                }
                lsr[i] += p0 + p1 + p2 + p3;
                __half2 a01 = __floats2half2_rn(p0, p1);
                __half2 a23 = __floats2half2_rn(p2, p3);
                uint2 u;
                u.x = *(unsigned*)&a01;
                u.y = *(unsigned*)&a23;
                *(uint2*)(phw + r * PHL + c0) = u;
            }
        }
        __syncwarp();

        // PV: this warp's P tile times the full V tile, hoisted P fragment
        #pragma unroll
        for (int k = 0; k < 4; ++k) {
            wmma::fragment<wmma::matrix_a, 16, 16, 16, __half, wmma::row_major> af;
            wmma::load_matrix_sync(af, phw + k * 16, PHL);
            #pragma unroll
            for (int j2 = 0; j2 < 8; ++j2) {
                wmma::fragment<wmma::matrix_b, 16, 16, 16, __half, wmma::row_major> bf;
                wmma::load_matrix_sync(bf, Vc + k * 16 * LDH + j2 * 16, LDH);
                wmma::mma_sync(Oacc[j2], af, bf, Oacc[j2]);
            }
        }
    }

    // Row sums: reduce over the 16 lanes sharing each row, publish per warp
    #pragma unroll
    for (int i = 0; i < 8; ++i) {
        float s = lsr[i];
        s += __shfl_xor_sync(0xffffffffu, s, 1);
        s += __shfl_xor_sync(0xffffffffu, s, 2);
        s += __shfl_xor_sync(0xffffffffu, s, 4);
        s += __shfl_xor_sync(0xffffffffu, s, 8);
        if (cl == 0) {
            lrowW[16 * w + 2 * i + half] = s;
        }
    }
    __syncwarp();

    float invr[8];
    #pragma unroll
    for (int i = 0; i < 8; ++i) {
        invr[i] = 1.0f / lrowW[16 * w + 2 * i + half];
    }

    // Output: stage O through the private scratch in two 64-wide chunks
    const long long obase = (bh * Sc + q0 + 16 * w + half) * (long long)Dc + c0;
    #pragma unroll
    for (int dhf = 0; dhf < 2; ++dhf) {
        __syncwarp();
        #pragma unroll
        for (int jj = 0; jj < 4; ++jj) {
            wmma::store_matrix_sync(pw + jj * 16, Oacc[dhf * 4 + jj], PFL,
                                    wmma::mem_row_major);
        }
        __syncwarp();
        #pragma unroll
        for (int i = 0; i < 8; ++i) {
            int r = 2 * i + half;
            float4 t = *(const float4*)(pw + r * PFL + c0);
            t.x *= invr[i];
            t.y *= invr[i];
            t.z *= invr[i];
            t.w *= invr[i];
            *(float4*)(outg + obase + 2 * i * (long long)Dc + dhf * 64) = t;
        }
    }
}

// Kernel 2: normalize each attn row in place (measured at DRAM roofline)
__global__ __launch_bounds__(256, 8)
void attn_norm_kernel(float* __restrict__ attn) {
    const long long row = blockIdx.x;
    float4* rp = (float4*)(attn + row * (long long)Sc);
    const int t = threadIdx.x;

    float4 a = rp[t];
    float4 b = rp[t + 256];
    float s = a.x + a.y + a.z + a.w + b.x + b.y + b.z + b.w;
    #pragma unroll
    for (int o = 16; o > 0; o >>= 1) {
        s += __shfl_xor_sync(0xffffffffu, s, o);
    }

    __shared__ float red[8];
    if ((t & 31) == 0) {
        red[t >> 5] = s;
    }
    __syncthreads();
    float tot = red[0] + red[1] + red[2] + red[3] + red[4] + red[5] + red[6] + red[7];
    float inv = 1.0f / tot;

    a.x *= inv; a.y *= inv; a.z *= inv; a.w *= inv;
    b.x *= inv; b.y *= inv; b.z *= inv; b.w *= inv;
    rp[t] = a;
    rp[t + 256] = b;
}

extern "C" void kernel_launch(void* const* d_in, const int* in_sizes, int n_in,
                              void* d_out, int out_size) {
    const float* q = (const float*)d_in[0];
    const float* k = (const float*)d_in[1];
    const float* v = (const float*)d_in[2];
    const float* m = (const float*)d_in[3];
    float* out = (float*)d_out;

    const long long OUT_ELE = (long long)Bc * Hc * Sc * Dc;
    float* attn = ((long long)out_size > OUT_ELE) ? (out + OUT_ELE) : nullptr;

    cudaFuncSetAttribute(attn_main_kernel,
                         cudaFuncAttributeMaxDynamicSharedMemorySize, SMEM_BYTES);
    cudaFuncSetAttribute(attn_main_kernel,
                         cudaFuncAttributePreferredSharedMemoryCarveout, 100);

    cvt_kernel<<<NTOT / 4 / 256, 256>>>((const float4*)q, (const float4*)k,
                                        (const float4*)v);

    dim3 grid1(Hc, Sc / TQ, Bc);
    attn_main_kernel<<<grid1, THREADS, SMEM_BYTES>>>(m, out, attn);

    if (attn) {
        attn_norm_kernel<<<(long long)Bc * Hc * Sc, 256>>>(attn);
    }
}

// round 14
// speedup vs baseline: 1.0508x; 1.0414x over previous
#include <cuda_runtime.h>
#include <cuda_fp16.h>
#include <mma.h>

using namespace nvcuda;

// Problem constants
#define Bc 4
#define Hc 16
#define Sc 2048
#define Dc 128
#define NTOT (Bc * Hc * Sc * Dc)

// Tiling (kernel A = round-7 proven shape)
#define TQ 64
#define TK 64
#define THREADS 512
#define NKT (Sc / TK)
#define LDH  136
#define PLDF 68
#define PLDH 72
#define MLD  64
#define OLDF 132

// Kernel A smem layout (bytes) — identical to round 7
#define QH_OFF   0
#define KH_OFF   (QH_OFF + TQ * LDH * 2)
#define VH_OFF   (KH_OFF + TK * LDH * 2)
#define PSF_OFF  (VH_OFF + TK * LDH * 2)
#define PSH_OFF  (PSF_OFF + TQ * PLDF * 4)
#define MS_OFF   (PSH_OFF + TQ * PLDH * 2)
#define LROW_OFF (MS_OFF + 2 * TQ * MLD * 4)
#define SMEM_BYTES (LROW_OFF + TQ * 4)          // 95,488 B -> 2 CTAs/SM

// Kernel B smem layout (bytes): Q tile, double-buffered K, S scratch
#define BQ_OFF  0
#define BK_OFF  (TQ * LDH * 2)
#define BPS_OFF (BK_OFF + 2 * TK * LDH * 2)
#define BSMEM_BYTES (BPS_OFF + TQ * PLDF * 4)   // 69,632 B -> 2 CTAs/SM

// fp16 copies of Q/K/V and per-row inverse sums. Static device scratch.
__device__ __half g_qh[NTOT];
__device__ __half g_kh[NTOT];
__device__ __half g_vh[NTOT];
__device__ float  g_inv[Bc * Hc * Sc];

__device__ __forceinline__ void cp_async16(void* s, const void* g) {
    unsigned sa = (unsigned)__cvta_generic_to_shared(s);
    asm volatile("cp.async.cg.shared.global [%0],[%1],16;\n" ::"r"(sa), "l"(g));
}
__device__ __forceinline__ void cp_commit() { asm volatile("cp.async.commit_group;\n"); }
__device__ __forceinline__ void cp_wait0() { asm volatile("cp.async.wait_group 0;\n"); }
__device__ __forceinline__ void cp_wait1() { asm volatile("cp.async.wait_group 1;\n"); }

// exp for small x via degree-6 Taylor; __expf fallback for the rare tail
__device__ __forceinline__ float exp_small(float x) {
    float pe = 1.388888889e-3f;
    pe = fmaf(pe, x, 8.333333333e-3f);
    pe = fmaf(pe, x, 4.166666667e-2f);
    pe = fmaf(pe, x, 1.666666667e-1f);
    pe = fmaf(pe, x, 0.5f);
    pe = fmaf(pe, x, 1.0f);
    pe = fmaf(pe, x, 1.0f);
    if (fabsf(x) > 0.5f) {
        pe = __expf(x);
    }
    return pe;
}

// Pre-pass: fp32 to fp16 RN conversion of Q, K, V (measured 84% DRAM, 38us)
__global__ __launch_bounds__(256)
void cvt_kernel(const float4* __restrict__ q,
                const float4* __restrict__ k,
                const float4* __restrict__ v) {
    int i = blockIdx.x * blockDim.x + threadIdx.x;
    float4 a;
    __half2 h0, h1;
    uint2 u;

    a = q[i];
    h0 = __floats2half2_rn(a.x, a.y);
    h1 = __floats2half2_rn(a.z, a.w);
    u.x = *(unsigned*)&h0;
    u.y = *(unsigned*)&h1;
    ((uint2*)g_qh)[i] = u;

    a = k[i];
    h0 = __floats2half2_rn(a.x, a.y);
    h1 = __floats2half2_rn(a.z, a.w);
    u.x = *(unsigned*)&h0;
    u.y = *(unsigned*)&h1;
    ((uint2*)g_kh)[i] = u;

    a = v[i];
    h0 = __floats2half2_rn(a.x, a.y);
    h1 = __floats2half2_rn(a.z, a.w);
    u.x = *(unsigned*)&h0;
    u.y = *(unsigned*)&h1;
    ((uint2*)g_vh)[i] = u;
}

// Kernel A: round-7 main kernel, attn stores removed, writes g_inv instead.
__global__ __launch_bounds__(THREADS, 2)
void attn_main_kernel(const float* __restrict__ mg,
                      float* __restrict__ outg) {
    extern __shared__ char sm[];
    __half* Qh   = (__half*)(sm + QH_OFF);
    __half* Kh   = (__half*)(sm + KH_OFF);
    __half* Vh   = (__half*)(sm + VH_OFF);
    float*  Psf  = (float*)(sm + PSF_OFF);
    __half* Psh  = (__half*)(sm + PSH_OFF);
    float*  Ms   = (float*)(sm + MS_OFF);
    float*  lrow = (float*)(sm + LROW_OFF);

    const int hh = blockIdx.x;
    const int qt = blockIdx.y;
    const int b  = blockIdx.z;
    const int tid  = threadIdx.x;
    const int warp = tid >> 5;
    const int q0   = qt * TQ;

    const long long bh = (long long)b * Hc + hh;
    const __half* qptr  = g_qh + (bh * Sc + q0) * (long long)Dc;
    const __half* kbase = g_kh + bh * Sc * (long long)Dc;
    const __half* vbase = g_vh + bh * Sc * (long long)Dc;
    const float*  mbase = mg + ((long long)b * Sc + q0) * (long long)Sc;

    // Prologue: cp.async Q tile (fp16, 16 KB); covered by the loop's first wait
    {
        int r = tid >> 4;
        int c8 = (tid & 15) * 8;
        cp_async16(Qh + r * LDH + c8, qptr + (long long)r * Dc + c8);
        r += 32;
        cp_async16(Qh + r * LDH + c8, qptr + (long long)r * Dc + c8);
    }
    if (tid < TQ) {
        lrow[tid] = 0.0f;
    }

    const int ti = warp >> 2;
    const int tj = warp & 3;

    wmma::fragment<wmma::accumulator, 16, 16, 16, float> Oacc[2];
    wmma::fill_fragment(Oacc[0], 0.0f);
    wmma::fill_fragment(Oacc[1], 0.0f);

    for (int kt = 0; kt < NKT; ++kt) {
        __syncthreads();   // prev iter's PV reads of Kh/Vh/Psh complete

        // cp.async K/V (fp16 direct) + mask tile
        {
            const __half* kp = kbase + (long long)kt * TK * Dc;
            const __half* vp = vbase + (long long)kt * TK * Dc;
            int r = tid >> 4;
            int c8 = (tid & 15) * 8;
            cp_async16(Kh + r * LDH + c8, kp + (long long)r * Dc + c8);
            cp_async16(Vh + r * LDH + c8, vp + (long long)r * Dc + c8);
            r += 32;
            cp_async16(Kh + r * LDH + c8, kp + (long long)r * Dc + c8);
            cp_async16(Vh + r * LDH + c8, vp + (long long)r * Dc + c8);

            const float* mp = mbase + (long long)kt * TK;
            int rm = tid >> 4;
            int cm = (tid & 15) * 4;
            cp_async16(Ms + rm * MLD + cm, mp + (long long)rm * Sc + cm);
            rm += 32;
            cp_async16(Ms + rm * MLD + cm, mp + (long long)rm * Sc + cm);
        }
        cp_commit();
        cp_wait0();
        __syncthreads();   // Qh/Kh/Vh/Ms visible

        // Scores: S = Q * K^T
        {
            wmma::fragment<wmma::accumulator, 16, 16, 16, float> Sacc;
            wmma::fill_fragment(Sacc, 0.0f);
            #pragma unroll
            for (int k = 0; k < Dc / 16; ++k) {
                wmma::fragment<wmma::matrix_a, 16, 16, 16, __half, wmma::row_major> af;
                wmma::fragment<wmma::matrix_b, 16, 16, 16, __half, wmma::col_major> bf;
                wmma::load_matrix_sync(af, Qh + ti * 16 * LDH + k * 16, LDH);
                wmma::load_matrix_sync(bf, Kh + tj * 16 * LDH + k * 16, LDH);
                wmma::mma_sync(Sacc, af, bf, Sacc);
            }
            wmma::store_matrix_sync(Psf + ti * 16 * PLDF + tj * 16, Sacc, PLDF,
                                    wmma::mem_row_major);
        }
        __syncthreads();   // Psf + mask visible

        // Elementwise: p = mask ? 0 : exp(s/128); rowsum; P->fp16 (no attn store)
        {
            const int r  = tid >> 3;
            const int c0 = (tid & 7) * 8;
            const float* mrow = Ms + (tid >> 3) * MLD + c0;
            const float* srow = Psf + r * PLDF + c0;
            float lsum = 0.0f;
            __half2 ph[4];
            #pragma unroll
            for (int cc = 0; cc < 2; ++cc) {
                float4 s4 = *(const float4*)(srow + cc * 4);
                float4 m4 = *(const float4*)(mrow + cc * 4);
                float p0 = exp_small(s4.x * 0.0078125f);
                float p1 = exp_small(s4.y * 0.0078125f);
                float p2 = exp_small(s4.z * 0.0078125f);
                float p3 = exp_small(s4.w * 0.0078125f);
                p0 = (m4.x != 0.0f) ? 0.0f : p0;
                p1 = (m4.y != 0.0f) ? 0.0f : p1;
                p2 = (m4.z != 0.0f) ? 0.0f : p2;
                p3 = (m4.w != 0.0f) ? 0.0f : p3;
                lsum += p0 + p1 + p2 + p3;
                ph[cc * 2 + 0] = __floats2half2_rn(p0, p1);
                ph[cc * 2 + 1] = __floats2half2_rn(p2, p3);
            }
            uint4 u;
            u.x = *(unsigned*)&ph[0];
            u.y = *(unsigned*)&ph[1];
            u.z = *(unsigned*)&ph[2];
            u.w = *(unsigned*)&ph[3];
            *(uint4*)(Psh + r * PLDH + c0) = u;

            lsum += __shfl_xor_sync(0xffffffffu, lsum, 1);
            lsum += __shfl_xor_sync(0xffffffffu, lsum, 2);
            lsum += __shfl_xor_sync(0xffffffffu, lsum, 4);
            if ((tid & 7) == 0) {
                lrow[r] += lsum;
            }
        }
        __syncthreads();   // Psh visible

        // PV: O += P * V
        #pragma unroll
        for (int k = 0; k < TK / 16; ++k) {
            wmma::fragment<wmma::matrix_a, 16, 16, 16, __half, wmma::row_major> af;
            wmma::load_matrix_sync(af, Psh + ti * 16 * PLDH + k * 16, PLDH);
            #pragma unroll
            for (int jj = 0; jj < 2; ++jj) {
                wmma::fragment<wmma::matrix_b, 16, 16, 16, __half, wmma::row_major> bf;
                wmma::load_matrix_sync(bf, Vh + k * 16 * LDH + (tj * 2 + jj) * 16, LDH);
                wmma::mma_sync(Oacc[jj], af, bf, Oacc[jj]);
            }
        }
    }

    __syncthreads();
    float* Of = (float*)(sm + KH_OFF);
    #pragma unroll
    for (int jj = 0; jj < 2; ++jj) {
        wmma::store_matrix_sync(Of + ti * 16 * OLDF + (tj * 2 + jj) * 16, Oacc[jj],
                                OLDF, wmma::mem_row_major);
    }
    __syncthreads();

    {
        const int r  = tid >> 3;
        const int c0 = (tid & 7) * 16;
        const float inv = 1.0f / lrow[r];
        if ((tid & 7) == 0) {
            g_inv[bh * Sc + q0 + r] = inv;
        }
        float* orow = outg + (bh * Sc + q0 + r) * (long long)Dc;
        #pragma unroll
        for (int cc = 0; cc < 4; ++cc) {
            int c = c0 + cc * 4;
            float4 o4 = *(const float4*)(Of + r * OLDF + c);
            o4.x *= inv;
            o4.y *= inv;
            o4.z *= inv;
            o4.w *= inv;
            *(float4*)(orow + c) = o4;
        }
    }
}

// Kernel B: recompute scores, write NORMALIZED attn once (no norm pass needed)
__global__ __launch_bounds__(THREADS, 2)
void attn_scores_kernel(const float* __restrict__ mg,
                        float* __restrict__ attng) {
    extern __shared__ char sm[];
    __half* Qh  = (__half*)(sm + BQ_OFF);
    __half* Kh  = (__half*)(sm + BK_OFF);    // 2 stages
    float*  Psf = (float*)(sm + BPS_OFF);

    const int hh = blockIdx.x;
    const int qt = blockIdx.y;
    const int b  = blockIdx.z;
    const int tid  = threadIdx.x;
    const int warp = tid >> 5;
    const int q0   = qt * TQ;

    const long long bh = (long long)b * Hc + hh;
    const __half* qptr  = g_qh + (bh * Sc + q0) * (long long)Dc;
    const __half* kbase = g_kh + bh * Sc * (long long)Dc;

    const int ti = warp >> 2;
    const int tj = warp & 3;

    // Prologue: Q tile, then K tile 0 into stage 0
    {
        int r = tid >> 4;
        int c8 = (tid & 15) * 8;
        cp_async16(Qh + r * LDH + c8, qptr + (long long)r * Dc + c8);
        r += 32;
        cp_async16(Qh + r * LDH + c8, qptr + (long long)r * Dc + c8);
    }
    cp_commit();
    {
        int r = tid >> 4;
        int c8 = (tid & 15) * 8;
        cp_async16(Kh + r * LDH + c8, kbase + (long long)r * Dc + c8);
        r += 32;
        cp_async16(Kh + r * LDH + c8, kbase + (long long)r * Dc + c8);
    }
    cp_commit();

    // Per-thread row assignment for the elementwise phase
    const int r  = tid >> 3;
    const int c0 = (tid & 7) * 8;
    const float invr = g_inv[bh * Sc + q0 + r];
    const float* mrow = mg + ((long long)b * Sc + q0 + r) * (long long)Sc + c0;
    float* arow = attng + (bh * Sc + q0 + r) * (long long)Sc + c0;

    for (int kt = 0; kt < NKT; ++kt) {
        if (kt + 1 < NKT) {
            const __half* kp = kbase + (long long)(kt + 1) * TK * Dc;
            __half* kd = Kh + ((kt + 1) & 1) * TK * LDH;
            int rr = tid >> 4;
            int c8 = (tid & 15) * 8;
            cp_async16(kd + rr * LDH + c8, kp + (long long)rr * Dc + c8);
            rr += 32;
            cp_async16(kd + rr * LDH + c8, kp + (long long)rr * Dc + c8);
            cp_commit();
            cp_wait1();
        } else {
            cp_wait0();
        }
        __syncthreads();   // stage kt (and Q on first iter) ready; Psf reads done

        const __half* Kc = Kh + (kt & 1) * TK * LDH;

        // S = Q K^T for this warp's 16x16 subtile
        {
            wmma::fragment<wmma::accumulator, 16, 16, 16, float> Sacc;
            wmma::fill_fragment(Sacc, 0.0f);
            #pragma unroll
            for (int k = 0; k < Dc / 16; ++k) {
                wmma::fragment<wmma::matrix_a, 16, 16, 16, __half, wmma::row_major> af;
                wmma::fragment<wmma::matrix_b, 16, 16, 16, __half, wmma::col_major> bf;
                wmma::load_matrix_sync(af, Qh + ti * 16 * LDH + k * 16, LDH);
                wmma::load_matrix_sync(bf, Kc + tj * 16 * LDH + k * 16, LDH);
                wmma::mma_sync(Sacc, af, bf, Sacc);
            }
            wmma::store_matrix_sync(Psf + ti * 16 * PLDF + tj * 16, Sacc, PLDF,
                                    wmma::mem_row_major);
        }
        __syncthreads();   // Psf visible

        // Elementwise: attn = mask ? 0 : exp(s/128) * invr  (normalized, final)
        {
            const float* srow = Psf + r * PLDF + c0;
            const float* mk = mrow + (long long)kt * TK;
            float* ak = arow + (long long)kt * TK;
            #pragma unroll
            for (int cc = 0; cc < 2; ++cc) {
                float4 s4 = *(const float4*)(srow + cc * 4);
                float4 m4 = *(const float4*)(mk + cc * 4);
                float p0 = exp_small(s4.x * 0.0078125f) * invr;
                float p1 = exp_small(s4.y * 0.0078125f) * invr;
                float p2 = exp_small(s4.z * 0.0078125f) * invr;
                float p3 = exp_small(s4.w * 0.0078125f) * invr;
                p0 = (m4.x != 0.0f) ? 0.0f : p0;
                p1 = (m4.y != 0.0f) ? 0.0f : p1;
                p2 = (m4.z != 0.0f) ? 0.0f : p2;
                p3 = (m4.w != 0.0f) ? 0.0f : p3;
                *(float4*)(ak + cc * 4) = make_float4(p0, p1, p2, p3);
            }
        }
    }
}

extern "C" void kernel_launch(void* const* d_in, const int* in_sizes, int n_in,
                              void* d_out, int out_size) {
    const float* q = (const float*)d_in[0];
    const float* k = (const float*)d_in[1];
    const float* v = (const float*)d_in[2];
    const float* m = (const float*)d_in[3];
    float* out = (float*)d_out;

    const long long OUT_ELE = (long long)Bc * Hc * Sc * Dc;
    float* attn = ((long long)out_size > OUT_ELE) ? (out + OUT_ELE) : nullptr;

    cudaFuncSetAttribute(attn_main_kernel,
                         cudaFuncAttributeMaxDynamicSharedMemorySize, SMEM_BYTES);
    cudaFuncSetAttribute(attn_main_kernel,
                         cudaFuncAttributePreferredSharedMemoryCarveout, 100);
    cudaFuncSetAttribute(attn_scores_kernel,
                         cudaFuncAttributeMaxDynamicSharedMemorySize, BSMEM_BYTES);
    cudaFuncSetAttribute(attn_scores_kernel,
                         cudaFuncAttributePreferredSharedMemoryCarveout, 100);

    cvt_kernel<<<NTOT / 4 / 256, 256>>>((const float4*)q, (const float4*)k,
                                        (const float4*)v);

    dim3 grid1(Hc, Sc / TQ, Bc);
    attn_main_kernel<<<grid1, THREADS, SMEM_BYTES>>>(m, out);

    if (attn) {
        attn_scores_kernel<<<grid1, THREADS, BSMEM_BYTES>>>(m, attn);
    }
}

// round 15
// speedup vs baseline: 1.4640x; 1.3933x over previous
#include <cuda_runtime.h>
#include <cuda_fp16.h>
#include <mma.h>

using namespace nvcuda;

// Problem constants
#define Bc 4
#define Hc 16
#define Sc 2048
#define Dc 128
#define NTOT (Bc * Hc * Sc * Dc)

// Tiling (round-7 proven shape + double-buffered K/V)
#define TQ 64
#define TK 64
#define THREADS 512
#define NKT (Sc / TK)
#define LDH  136
#define PLDF 68
#define PLDH 72
#define OLDF 132

// smem layout (bytes)
#define QH_OFF   0
#define KV_OFF   (TQ * LDH * 2)                 // 17408; 2 stages of (K tile, V tile)
#define KVSTAGE  (2 * TK * LDH * 2)             // 34816 per stage
#define PSF_OFF  (KV_OFF + 2 * KVSTAGE)         // 87040
#define PSH_OFF  (PSF_OFF + TQ * PLDF * 4)      // 104448
#define SMEM_BYTES (PSH_OFF + TQ * PLDH * 2)    // 113664 -> 2 CTAs/SM

// fp16 copies of Q/K/V (pre-pass output). Static device scratch: allowed.
__device__ __half g_qh[NTOT];
__device__ __half g_kh[NTOT];
__device__ __half g_vh[NTOT];

__device__ __forceinline__ void cp_async16(void* s, const void* g) {
    unsigned sa = (unsigned)__cvta_generic_to_shared(s);
    asm volatile("cp.async.cg.shared.global [%0],[%1],16;\n" ::"r"(sa), "l"(g));
}
__device__ __forceinline__ void cp_commit() { asm volatile("cp.async.commit_group;\n"); }
__device__ __forceinline__ void cp_wait0() { asm volatile("cp.async.wait_group 0;\n"); }
__device__ __forceinline__ void cp_wait1() { asm volatile("cp.async.wait_group 1;\n"); }

// exp for small x via degree-6 Taylor; __expf fallback for the rare tail
__device__ __forceinline__ float exp_small(float x) {
    float pe = 1.388888889e-3f;
    pe = fmaf(pe, x, 8.333333333e-3f);
    pe = fmaf(pe, x, 4.166666667e-2f);
    pe = fmaf(pe, x, 1.666666667e-1f);
    pe = fmaf(pe, x, 0.5f);
    pe = fmaf(pe, x, 1.0f);
    pe = fmaf(pe, x, 1.0f);
    if (fabsf(x) > 0.5f) {
        pe = __expf(x);
    }
    return pe;
}

// Pre-pass: fp32 to fp16 RN conversion of Q, K, V (measured 84% DRAM, 38us)
__global__ __launch_bounds__(256)
void cvt_kernel(const float4* __restrict__ q,
                const float4* __restrict__ k,
                const float4* __restrict__ v) {
    int i = blockIdx.x * blockDim.x + threadIdx.x;
    float4 a;
    __half2 h0, h1;
    uint2 u;

    a = q[i];
    h0 = __floats2half2_rn(a.x, a.y);
    h1 = __floats2half2_rn(a.z, a.w);
    u.x = *(unsigned*)&h0;
    u.y = *(unsigned*)&h1;
    ((uint2*)g_qh)[i] = u;

    a = k[i];
    h0 = __floats2half2_rn(a.x, a.y);
    h1 = __floats2half2_rn(a.z, a.w);
    u.x = *(unsigned*)&h0;
    u.y = *(unsigned*)&h1;
    ((uint2*)g_kh)[i] = u;

    a = v[i];
    h0 = __floats2half2_rn(a.x, a.y);
    h1 = __floats2half2_rn(a.z, a.w);
    u.x = *(unsigned*)&h0;
    u.y = *(unsigned*)&h1;
    ((uint2*)g_vh)[i] = u;
}

__global__ __launch_bounds__(THREADS, 2)
void attn_main_kernel(const float* __restrict__ mg,
                      float* __restrict__ outg,
                      float* __restrict__ attng) {
    extern __shared__ char sm[];
    __half* Qh  = (__half*)(sm + QH_OFF);
    __half* kvs = (__half*)(sm + KV_OFF);
    float*  Psf = (float*)(sm + PSF_OFF);
    __half* Psh = (__half*)(sm + PSH_OFF);

    const int hh = blockIdx.x;   // head fastest: mask slice L2-reused across heads
    const int qt = blockIdx.y;
    const int b  = blockIdx.z;
    const int tid  = threadIdx.x;
    const int warp = tid >> 5;
    const int q0   = qt * TQ;

    const long long bh = (long long)b * Hc + hh;
    const __half* qptr  = g_qh + (bh * Sc + q0) * (long long)Dc;
    const __half* kbase = g_kh + bh * Sc * (long long)Dc;
    const __half* vbase = g_vh + bh * Sc * (long long)Dc;

    // Prologue group 0: Q tile + K0/V0 into stage 0
    {
        int r = tid >> 4;
        int c8 = (tid & 15) * 8;
        cp_async16(Qh + r * LDH + c8, qptr + (long long)r * Dc + c8);
        cp_async16(kvs + r * LDH + c8, kbase + (long long)r * Dc + c8);
        cp_async16(kvs + TK * LDH + r * LDH + c8, vbase + (long long)r * Dc + c8);
        r += 32;
        cp_async16(Qh + r * LDH + c8, qptr + (long long)r * Dc + c8);
        cp_async16(kvs + r * LDH + c8, kbase + (long long)r * Dc + c8);
        cp_async16(kvs + TK * LDH + r * LDH + c8, vbase + (long long)r * Dc + c8);
    }
    cp_commit();

    const int ti = warp >> 2;
    const int tj = warp & 3;

    wmma::fragment<wmma::accumulator, 16, 16, 16, float> Oacc[2];
    wmma::fill_fragment(Oacc[0], 0.0f);
    wmma::fill_fragment(Oacc[1], 0.0f);
    float lsum = 0.0f;   // per-thread rowsum partial, reduced at the end

    // Exp-phase addressing (same mapping as round 7, mask straight from gmem)
    const int er  = tid >> 3;
    const int ec0 = (tid & 7) * 8;
    const float* mrow = mg + ((long long)b * Sc + q0 + er) * (long long)Sc + ec0;
    float* arow = attng ? (attng + (bh * Sc + q0 + er) * (long long)Sc + ec0) : nullptr;

    for (int kt = 0; kt < NKT; ++kt) {
        __syncthreads();   // all warps done reading the stage we are about to refill

        if (kt + 1 < NKT) {
            const __half* kp = kbase + (long long)(kt + 1) * TK * Dc;
            const __half* vp = vbase + (long long)(kt + 1) * TK * Dc;
            __half* kd = kvs + ((kt + 1) & 1) * (KVSTAGE / 2);
            int r = tid >> 4;
            int c8 = (tid & 15) * 8;
            cp_async16(kd + r * LDH + c8, kp + (long long)r * Dc + c8);
            cp_async16(kd + TK * LDH + r * LDH + c8, vp + (long long)r * Dc + c8);
            r += 32;
            cp_async16(kd + r * LDH + c8, kp + (long long)r * Dc + c8);
            cp_async16(kd + TK * LDH + r * LDH + c8, vp + (long long)r * Dc + c8);
            cp_commit();
            cp_wait1();    // stage kt arrived; stage kt+1 still in flight
        } else {
            cp_wait0();
        }
        __syncthreads();   // stage kt (and Q on first iter) visible to all warps

        const __half* Kc = kvs + (kt & 1) * (KVSTAGE / 2);
        const __half* Vc = Kc + TK * LDH;

        // Scores: S = Q * K^T
        {
            wmma::fragment<wmma::accumulator, 16, 16, 16, float> Sacc;
            wmma::fill_fragment(Sacc, 0.0f);
            #pragma unroll
            for (int k = 0; k < Dc / 16; ++k) {
                wmma::fragment<wmma::matrix_a, 16, 16, 16, __half, wmma::row_major> af;
                wmma::fragment<wmma::matrix_b, 16, 16, 16, __half, wmma::col_major> bf;
                wmma::load_matrix_sync(af, Qh + ti * 16 * LDH + k * 16, LDH);
                wmma::load_matrix_sync(bf, Kc + tj * 16 * LDH + k * 16, LDH);
                wmma::mma_sync(Sacc, af, bf, Sacc);
            }
            wmma::store_matrix_sync(Psf + ti * 16 * PLDF + tj * 16, Sacc, PLDF,
                                    wmma::mem_row_major);
        }
        __syncthreads();   // Psf visible

        // Elementwise: p = mask ? 0 : exp(s/128); attn store; rowsum; P->fp16
        {
            const float* srow = Psf + er * PLDF + ec0;
            const float* mk = mrow + (long long)kt * TK;
            float* ak = arow ? (arow + (long long)kt * TK) : nullptr;
            __half2 ph[4];
            #pragma unroll
            for (int cc = 0; cc < 2; ++cc) {
                float4 s4 = *(const float4*)(srow + cc * 4);
                float4 m4 = *(const float4*)(mk + cc * 4);
                float p0 = exp_small(s4.x * 0.0078125f);
                float p1 = exp_small(s4.y * 0.0078125f);
                float p2 = exp_small(s4.z * 0.0078125f);
                float p3 = exp_small(s4.w * 0.0078125f);
                p0 = (m4.x != 0.0f) ? 0.0f : p0;
                p1 = (m4.y != 0.0f) ? 0.0f : p1;
                p2 = (m4.z != 0.0f) ? 0.0f : p2;
                p3 = (m4.w != 0.0f) ? 0.0f : p3;
                if (ak) {
                    *(float4*)(ak + cc * 4) = make_float4(p0, p1, p2, p3);
                }
                lsum += p0 + p1 + p2 + p3;
                ph[cc * 2 + 0] = __floats2half2_rn(p0, p1);
                ph[cc * 2 + 1] = __floats2half2_rn(p2, p3);
            }
            uint4 u;
            u.x = *(unsigned*)&ph[0];
            u.y = *(unsigned*)&ph[1];
            u.z = *(unsigned*)&ph[2];
            u.w = *(unsigned*)&ph[3];
            *(uint4*)(Psh + er * PLDH + ec0) = u;
        }
        __syncthreads();   // Psh visible

        // PV: O += P * V
        #pragma unroll
        for (int k = 0; k < TK / 16; ++k) {
            wmma::fragment<wmma::matrix_a, 16, 16, 16, __half, wmma::row_major> af;
            wmma::load_matrix_sync(af, Psh + ti * 16 * PLDH + k * 16, PLDH);
            #pragma unroll
            for (int jj = 0; jj < 2; ++jj) {
                wmma::fragment<wmma::matrix_b, 16, 16, 16, __half, wmma::row_major> bf;
                wmma::load_matrix_sync(bf, Vc + k * 16 * LDH + (tj * 2 + jj) * 16, LDH);
                wmma::mma_sync(Oacc[jj], af, bf, Oacc[jj]);
            }
        }
    }

    // Row sums: the 8 lanes sharing row er reduce among themselves
    lsum += __shfl_xor_sync(0xffffffffu, lsum, 1);
    lsum += __shfl_xor_sync(0xffffffffu, lsum, 2);
    lsum += __shfl_xor_sync(0xffffffffu, lsum, 4);
    const float inv = 1.0f / lsum;

    __syncthreads();
    // Stage O (fp32) into the KV region, then normalized write
    float* Of = (float*)(sm + KV_OFF);
    #pragma unroll
    for (int jj = 0; jj < 2; ++jj) {
        wmma::store_matrix_sync(Of + ti * 16 * OLDF + (tj * 2 + jj) * 16, Oacc[jj],
                                OLDF, wmma::mem_row_major);
    }
    __syncthreads();

    {
        const int c0 = (tid & 7) * 16;
        float* orow = outg + (bh * Sc + q0 + er) * (long long)Dc;
        #pragma unroll
        for (int cc = 0; cc < 4; ++cc) {
            int c = c0 + cc * 4;
            float4 o4 = *(const float4*)(Of + er * OLDF + c);
            o4.x *= inv;
            o4.y *= inv;
            o4.z *= inv;
            o4.w *= inv;
            *(float4*)(orow + c) = o4;
        }
    }
}

// Kernel 2: normalize each attn row in place (measured at DRAM roofline)
__global__ __launch_bounds__(256, 8)
void attn_norm_kernel(float* __restrict__ attn) {
    const long long row = blockIdx.x;
    float4* rp = (float4*)(attn + row * (long long)Sc);
    const int t = threadIdx.x;

    float4 a = rp[t];
    float4 b = rp[t + 256];
    float s = a.x + a.y + a.z + a.w + b.x + b.y + b.z + b.w;
    #pragma unroll
    for (int o = 16; o > 0; o >>= 1) {
        s += __shfl_xor_sync(0xffffffffu, s, o);
    }

    __shared__ float red[8];
    if ((t & 31) == 0) {
        red[t >> 5] = s;
    }
    __syncthreads();
    float tot = red[0] + red[1] + red[2] + red[3] + red[4] + red[5] + red[6] + red[7];
    float inv = 1.0f / tot;

    a.x *= inv; a.y *= inv; a.z *= inv; a.w *= inv;
    b.x *= inv; b.y *= inv; b.z *= inv; b.w *= inv;
    rp[t] = a;
    rp[t + 256] = b;
}

extern "C" void kernel_launch(void* const* d_in, const int* in_sizes, int n_in,
                              void* d_out, int out_size) {
    const float* q = (const float*)d_in[0];
    const float* k = (const float*)d_in[1];
    const float* v = (const float*)d_in[2];
    const float* m = (const float*)d_in[3];
    float* out = (float*)d_out;

    const long long OUT_ELE = (long long)Bc * Hc * Sc * Dc;
    float* attn = ((long long)out_size > OUT_ELE) ? (out + OUT_ELE) : nullptr;

    cudaFuncSetAttribute(attn_main_kernel,
                         cudaFuncAttributeMaxDynamicSharedMemorySize, SMEM_BYTES);
    cudaFuncSetAttribute(attn_main_kernel,
                         cudaFuncAttributePreferredSharedMemoryCarveout, 100);

    cvt_kernel<<<NTOT / 4 / 256, 256>>>((const float4*)q, (const float4*)k,
                                        (const float4*)v);

    dim3 grid1(Hc, Sc / TQ, Bc);
    attn_main_kernel<<<grid1, THREADS, SMEM_BYTES>>>(m, out, attn);

    if (attn) {
        attn_norm_kernel<<<(long long)Bc * Hc * Sc, 256>>>(attn);
    }
}